// round 1
// baseline (speedup 1.0000x reference)
#include <cuda_runtime.h>
#include <stdint.h>

// Problem constants (fixed-shape problem: 48x48 grid, regular triangulation)
static constexpr int HH   = 48;
static constexpr int WW   = 48;
static constexpr int N_V  = HH * WW;                                          // 2304 vertices
static constexpr int N_E  = HH*(WW-1) + (HH-1)*WW + (HH-1)*(WW-1);            // 6721 edges
static constexpr int N_F  = 2*(HH-1)*(WW-1);                                  // 4418 triangles
static constexpr int M_S  = N_V + N_E + N_F;                                  // 13443 simplices

// Global scratch (no allocations allowed)
__device__ float              g_vals[M_S];
__device__ unsigned long long g_keys[M_S];
__device__ int                g_rank[M_S];
__device__ int                g_cof0[N_E];
__device__ int                g_cof1[N_E];
__device__ uint4              g_erec[N_E];   // sorted edge records

// Order-preserving map float -> uint32 (total order matching float <)
__device__ __forceinline__ unsigned int fsort(float x) {
    unsigned int u = __float_as_uint(x);
    return (u & 0x80000000u) ? ~u : (u | 0x80000000u);
}

// ---------------------------------------------------------------------------
// K1: per-simplex filtration values + sort keys; init coface arrays; zero out
// ---------------------------------------------------------------------------
__global__ void k_vals(const float* __restrict__ img,
                       const int*   __restrict__ edges,
                       const int*   __restrict__ tris,
                       float* __restrict__ out, int out_n)
{
    int s   = blockIdx.x * blockDim.x + threadIdx.x;
    int gsz = gridDim.x * blockDim.x;
    for (int o = s; o < out_n; o += gsz) out[o] = 0.0f;   // clear poisoned output
    if (s >= M_S) return;

    float v;
    if (s < N_V) {
        v = img[s];
    } else if (s < N_V + N_E) {
        int e = s - N_V;
        v = fmaxf(img[edges[2*e]], img[edges[2*e + 1]]);
        g_cof0[e] = 0x7fffffff;
        g_cof1[e] = -1;
    } else {
        int t = s - N_V - N_E;
        float mx = -__int_as_float(0x7f800000);
        #pragma unroll
        for (int k = 0; k < 3; k++) {
            int e = tris[3*t + k];
            mx = fmaxf(mx, fmaxf(img[edges[2*e]], img[edges[2*e + 1]]));
        }
        v = mx;
    }
    g_vals[s] = v;
    // key = (sortable value, original index). dim is monotone in index, so
    // this exactly reproduces lexsort((dims, vals)) with stable idx tiebreak.
    g_keys[s] = ((unsigned long long)fsort(v) << 32) | (unsigned int)s;
}

// ---------------------------------------------------------------------------
// K2: edge -> triangle coface map (each edge has 1 or 2 cofaces).
// atomicMin/atomicMax are order-independent => deterministic.
// ---------------------------------------------------------------------------
__global__ void k_cof(const int* __restrict__ tris)
{
    int t = blockIdx.x * blockDim.x + threadIdx.x;
    if (t >= N_F) return;
    #pragma unroll
    for (int k = 0; k < 3; k++) {
        int e = tris[3*t + k];
        atomicMin(&g_cof0[e], t);
        atomicMax(&g_cof1[e], t);
    }
}

// ---------------------------------------------------------------------------
// K3: rank by counting (all keys distinct). Each thread owns one simplex and
// counts keys < its own over shared-memory chunks (broadcast LDS, conflict-free).
// Edge threads also compute their rank-among-edges and emit a sorted edge record.
// ---------------------------------------------------------------------------
static constexpr int RCHUNK = 4096;

__global__ void k_rank(const int* __restrict__ edges)
{
    __shared__ unsigned long long sk[RCHUNK];
    int  s   = blockIdx.x * blockDim.x + threadIdx.x;
    bool act = (s < M_S);
    unsigned long long my = act ? g_keys[s] : 0ULL;

    int rank = 0, erank = 0;
    for (int cb = 0; cb < M_S; cb += RCHUNK) {
        int cnt = min(RCHUNK, M_S - cb);
        __syncthreads();
        for (int j = threadIdx.x; j < cnt; j += blockDim.x) sk[j] = g_keys[cb + j];
        __syncthreads();
        if (act) {
            for (int j = 0; j < cnt; j++) {
                bool lt = sk[j] < my;
                rank += lt;
                int g = cb + j;
                erank += (lt && g >= N_V && g < N_V + N_E);
            }
        }
    }
    if (!act) return;
    g_rank[s] = rank;

    if (s >= N_V && s < N_V + N_E) {
        int e  = s - N_V;
        int u  = edges[2*e], v = edges[2*e + 1];
        int c0 = g_cof0[e],  c1 = g_cof1[e];
        uint4 r;
        r.x = (unsigned)u | ((unsigned)v << 16);   // endpoints (< 2304, fit 16b)
        r.y = __float_as_uint(g_vals[s]);          // edge value
        r.z = (unsigned)rank;                      // global rank of this edge
        r.w = (unsigned)c0 | ((unsigned)c1 << 16); // cofaces; c0==c1 => boundary
        g_erec[erank] = r;
    }
}

// ---------------------------------------------------------------------------
// K4: single block. Stage everything into shared memory, then two concurrent
// serial union-finds:
//   warp0/lane0: dim-0 elder-rule UF over vertices, edges in increasing order
//   warp1/lane0: dim-1 via dual UF over triangles+outer face, decreasing order
// ---------------------------------------------------------------------------
static constexpr int SMEM_BYTES = N_E*16 + N_V*12 + (N_F + 1)*12; // 188212

__device__ __forceinline__ int uf_find(int* __restrict__ p, int x) {
    while (true) {
        int px = p[x];
        if (px == x) return x;
        int gx = p[px];           // path halving
        p[x] = gx;
        x = gx;
    }
}

__global__ void k_pair(const float* __restrict__ img, float* __restrict__ out)
{
    extern __shared__ int smbuf[];
    uint4* rec = (uint4*)smbuf;            // [N_E]
    int*   p0  = (int*)(rec + N_E);        // [N_V]  primal UF parent
    int*   bR0 = p0 + N_V;                 // [N_V]  birth rank at root
    float* bV0 = (float*)(bR0 + N_V);      // [N_V]  birth value at root
    int*   p1  = (int*)(bV0 + N_V);        // [N_F+1] dual UF parent (node N_F = outer face)
    int*   bR1 = p1 + (N_F + 1);
    float* bV1 = (float*)(bR1 + (N_F + 1));
    __shared__ float smin[256], smax[256];

    int tid = threadIdx.x;

    for (int i = tid; i < N_E; i += blockDim.x) rec[i] = g_erec[i];
    for (int v = tid; v < N_V; v += blockDim.x) {
        p0[v] = v; bR0[v] = g_rank[v]; bV0[v] = img[v];
    }
    for (int t = tid; t < N_F; t += blockDim.x) {
        p1[t] = t; bR1[t] = g_rank[N_V + N_E + t]; bV1[t] = g_vals[N_V + N_E + t];
    }
    if (tid == 0) { p1[N_F] = N_F; bR1[N_F] = M_S; bV1[N_F] = 0.0f; }

    // global min/max of filtration values (min = birth of essential H0 at row 0,
    // max = fmax used as its death)
    float inf = __int_as_float(0x7f800000);
    float lmin = inf, lmax = -inf;
    for (int i = tid; i < M_S; i += blockDim.x) {
        float x = g_vals[i];
        lmin = fminf(lmin, x); lmax = fmaxf(lmax, x);
    }
    smin[tid] = lmin; smax[tid] = lmax;
    __syncthreads();
    for (int st = 128; st > 0; st >>= 1) {
        if (tid < st) {
            smin[tid] = fminf(smin[tid], smin[tid + st]);
            smax[tid] = fmaxf(smax[tid], smax[tid + st]);
        }
        __syncthreads();
    }
    if (tid == 0) { out[0] = smin[0]; out[1] = smax[0]; }  // dgm0 row 0: essential
    __syncthreads();

    if (tid == 0) {
        // ---- dim 0: Kruskal elder rule, increasing key order ----
        for (int i = 0; i < N_E; i++) {
            uint4 r = rec[i];
            int u = (int)(r.x & 0xffffu), v = (int)(r.x >> 16);
            int ru = uf_find(p0, u);
            int rv = uf_find(p0, v);
            if (ru == rv) continue;                  // positive edge (H1 birth)
            if (bR0[ru] > bR0[rv]) { int t = ru; ru = rv; rv = t; }  // ru = elder
            int row = bR0[rv];                       // dying birth's sorted position
            out[(size_t)row * 2]     = bV0[rv];      // birth
            out[(size_t)row * 2 + 1] = __uint_as_float(r.y); // death = edge value
            p0[rv] = ru;
        }
    } else if (tid == 32) {
        // ---- dim 1 via dual: reversed-order UF on triangles + outer face ----
        const size_t base = (size_t)2 * M_S;
        for (int i = N_E - 1; i >= 0; i--) {
            uint4 r = rec[i];
            int c0 = (int)(r.w & 0xffffu), c1 = (int)(r.w >> 16);
            int a = c0;
            int b = (c1 == c0) ? N_F : c1;           // boundary edge -> outer face
            int ra = uf_find(p1, a);
            int rb = uf_find(p1, b);
            if (ra == rb) continue;                  // primal-negative edge
            // survivor = elder in reversed order = larger forward rank
            if (bR1[ra] < bR1[rb]) { int t = ra; ra = rb; rb = t; }  // ra survives
            int row = (int)r.z;                      // rank of the positive edge
            out[base + (size_t)row * 2]     = __uint_as_float(r.y); // birth = edge val
            out[base + (size_t)row * 2 + 1] = bV1[rb];              // death = tri val
            p1[rb] = ra;
        }
    }
}

// ---------------------------------------------------------------------------
extern "C" void kernel_launch(void* const* d_in, const int* in_sizes, int n_in,
                              void* d_out, int out_size)
{
    const float* img   = (const float*)d_in[0];
    const int*   edges = (const int*)d_in[1];
    const int*   tris  = (const int*)d_in[2];
    float*       out   = (float*)d_out;

    cudaFuncSetAttribute(k_pair, cudaFuncAttributeMaxDynamicSharedMemorySize, SMEM_BYTES);

    k_vals<<<(M_S + 255) / 256, 256>>>(img, edges, tris, out, out_size);
    k_cof <<<(N_F + 255) / 256, 256>>>(tris);
    k_rank<<<(M_S + 255) / 256, 256>>>(edges);
    k_pair<<<1, 256, SMEM_BYTES>>>(img, out);
}